// round 2
// baseline (speedup 1.0000x reference)
#include <cuda_runtime.h>
#include <math.h>

#define Gg   256
#define Nn   512
#define Ee   4096
#define FIN  64
#define FOUT 64
#define Cc   16
#define NK   (Nn * FOUT)          // 32768 flat features per graph
#define CSRE (Ee + Nn)            // edges + self-loops = 4608

// ---------------- scratch ----------------
__device__ float g_xw[(size_t)Gg * Nn * FOUT];     // x @ W^T
__device__ float g_h [(size_t)Gg * Nn * FOUT];     // relu(aggregate + bias)
__device__ int   g_srow [(size_t)Gg * CSRE];       // CSR source node per entry
__device__ float g_snorm[(size_t)Gg * CSRE];       // CSR norm per entry
__device__ int   g_offx [(size_t)Gg * (Nn + 1)];   // CSR row offsets
__device__ float g_logits[(size_t)Gg * Cc];        // split-K partial logits

// ---------------------------------------------------------------------------
// K1: per-graph GEMM  xw[g] = x[g] (512x64) @ W^T (64x64)   (FFMA-bound)
// ---------------------------------------------------------------------------
__global__ __launch_bounds__(256) void k1_xw(const float* __restrict__ x,
                                             const float* __restrict__ w)
{
    __shared__ float Xt[64 * 68];   // Xt[k][n]
    __shared__ float Wt[64 * 68];   // Wt[k][o]

    const int g     = blockIdx.y;
    const int nbase = blockIdx.x * 64;
    const int t     = threadIdx.x;

    const float* xg = x + ((size_t)g * Nn + nbase) * FIN;

    for (int i = t; i < 4096; i += 256) {
        int r = i >> 6, k = i & 63;
        Xt[k * 68 + r] = xg[r * FIN + k];
        Wt[k * 68 + r] = w[r * FIN + k];
    }
    __syncthreads();

    const int o0 = (t & 15) * 4;
    const int n0 = (t >> 4) * 4;

    float acc[4][4];
    #pragma unroll
    for (int i = 0; i < 4; i++)
        #pragma unroll
        for (int j = 0; j < 4; j++) acc[i][j] = 0.f;

    #pragma unroll 8
    for (int k = 0; k < 64; k++) {
        float4 xv = *(const float4*)&Xt[k * 68 + n0];
        float4 wv = *(const float4*)&Wt[k * 68 + o0];
        float xs[4] = {xv.x, xv.y, xv.z, xv.w};
        float ws[4] = {wv.x, wv.y, wv.z, wv.w};
        #pragma unroll
        for (int i = 0; i < 4; i++)
            #pragma unroll
            for (int j = 0; j < 4; j++)
                acc[i][j] = fmaf(xs[i], ws[j], acc[i][j]);
    }

    float* outp = g_xw + ((size_t)g * Nn + nbase) * FOUT;
    #pragma unroll
    for (int i = 0; i < 4; i++)
        *(float4*)&outp[(size_t)(n0 + i) * FOUT + o0] =
            make_float4(acc[i][0], acc[i][1], acc[i][2], acc[i][3]);
}

// ---------------------------------------------------------------------------
// K2a: per-graph preprocessing -> CSR in global scratch (self-loop first entry)
// ---------------------------------------------------------------------------
__global__ __launch_bounds__(512) void k2a_csr(const int* __restrict__ ei)
{
    __shared__ int   cnt[Nn];
    __shared__ int   sc[Nn];
    __shared__ float dv[Nn];

    const int g   = blockIdx.x;
    const int tid = threadIdx.x;

    const int* rowp = ei + (size_t)g * 2 * Ee;
    const int* colp = rowp + Ee;

    cnt[tid] = 1;                       // self-loop counts toward degree
    __syncthreads();
    for (int e = tid; e < Ee; e += 512)
        atomicAdd(&cnt[colp[e]], 1);
    __syncthreads();

    const int myc = cnt[tid];
    const float d = rsqrtf((float)myc);
    dv[tid] = d;
    sc[tid] = myc;
    __syncthreads();

    for (int s = 1; s < Nn; s <<= 1) {
        int v = (tid >= s) ? sc[tid - s] : 0;
        __syncthreads();
        sc[tid] += v;
        __syncthreads();
    }
    const int incl = sc[tid];
    const int excl = incl - myc;
    g_offx[(size_t)g * (Nn + 1) + tid + 1] = incl;
    if (tid == 0) g_offx[(size_t)g * (Nn + 1)] = 0;
    if (tid < Cc) g_logits[g * Cc + tid] = 0.f;   // zero split-K accumulator

    const size_t base = (size_t)g * CSRE;
    g_srow [base + excl] = tid;                   // self-loop entry
    g_snorm[base + excl] = d * d;
    cnt[tid] = excl + 1;                          // write cursor
    __syncthreads();

    for (int e = tid; e < Ee; e += 512) {
        int r = rowp[e], c = colp[e];
        int pos = atomicAdd(&cnt[c], 1);
        g_srow [base + pos] = r;
        g_snorm[base + pos] = dv[r] * dv[c];
    }
}

// ---------------------------------------------------------------------------
// K2b: aggregation + bias + ReLU -> h.  grid (G, 4), warp-per-node, unroll x2.
// ---------------------------------------------------------------------------
__global__ __launch_bounds__(512) void k2b_agg(const float* __restrict__ conv_bias)
{
    __shared__ float bias_s[FOUT];

    const int g    = blockIdx.x;
    const int tid  = threadIdx.x;
    const int wid  = tid >> 5;
    const int lane = tid & 31;

    if (tid < FOUT) bias_s[tid] = conv_bias[tid];
    __syncthreads();

    const float2* xw2   = (const float2*)(g_xw + (size_t)g * NK);
    float2*       h2    = (float2*)      (g_h  + (size_t)g * NK);
    const int*    offx  = g_offx  + (size_t)g * (Nn + 1);
    const int*    srow  = g_srow  + (size_t)g * CSRE;
    const float*  snorm = g_snorm + (size_t)g * CSRE;

    const float bx0 = bias_s[lane * 2];
    const float bx1 = bias_s[lane * 2 + 1];

    const int nend = blockIdx.y * 128 + 128;
    for (int n = blockIdx.y * 128 + wid; n < nend; n += 16) {
        const int b  = offx[n];
        const int e2 = offx[n + 1];

        float ax = 0.f, ay = 0.f, cx = 0.f, cy = 0.f;
        int j = b;
        for (; j + 2 <= e2; j += 2) {
            int   r0  = srow[j],     r1  = srow[j + 1];
            float nm0 = snorm[j],    nm1 = snorm[j + 1];
            float2 v0 = __ldg(&xw2[r0 * 32 + lane]);
            float2 v1 = __ldg(&xw2[r1 * 32 + lane]);
            ax = fmaf(v0.x, nm0, ax);  ay = fmaf(v0.y, nm0, ay);
            cx = fmaf(v1.x, nm1, cx);  cy = fmaf(v1.y, nm1, cy);
        }
        if (j < e2) {
            int   r  = srow[j];
            float nm = snorm[j];
            float2 v = __ldg(&xw2[r * 32 + lane]);
            ax = fmaf(v.x, nm, ax);  ay = fmaf(v.y, nm, ay);
        }
        ax += cx;  ay += cy;

        ax = fmaxf(ax + bx0, 0.f);
        ay = fmaxf(ay + bx1, 0.f);
        h2[n * 32 + lane] = make_float2(ax, ay);
    }
}

// ---------------------------------------------------------------------------
// K3: classifier GEMM  logits += h[G, 32768] @ lw[C, 32768]^T
//     grid (128 ktiles, 2 gtiles), block 128; M=128 graphs, N=16, K=256/block.
//     smem tiles: hs transposed [k][g] (conflict-free float4), ls [k][c].
// ---------------------------------------------------------------------------
__global__ __launch_bounds__(128) void k3_cls(const float* __restrict__ lw)
{
    __shared__ float hs[64 * 128];   // [k][g]
    __shared__ float ls[64 * 16];    // [k][c]

    const int ktile = blockIdx.x;    // 0..127, 256 K each
    const int g0    = blockIdx.y * 128;
    const int tid   = threadIdx.x;

    const int gq = tid & 31;         // 32 graph groups (x4)
    const int cq = tid >> 5;         // 4 class groups (x4)

    float acc[4][4];
    #pragma unroll
    for (int i = 0; i < 4; i++)
        #pragma unroll
        for (int j = 0; j < 4; j++) acc[i][j] = 0.f;

    for (int ch = 0; ch < 4; ch++) {
        const int kbase = ktile * 256 + ch * 64;
        __syncthreads();
        // h chunk: 128 graphs x 64 k, store transposed
        for (int i = tid; i < 2048; i += 128) {
            int gg = i >> 4, kq = (i & 15) * 4;
            float4 v = *(const float4*)(g_h + (size_t)(g0 + gg) * NK + kbase + kq);
            hs[(kq + 0) * 128 + gg] = v.x;
            hs[(kq + 1) * 128 + gg] = v.y;
            hs[(kq + 2) * 128 + gg] = v.z;
            hs[(kq + 3) * 128 + gg] = v.w;
        }
        // lw chunk: 16 classes x 64 k (coalesced along k)
        for (int i = tid; i < 1024; i += 128) {
            int c = i >> 6, k = i & 63;
            ls[k * 16 + c] = lw[(size_t)c * NK + kbase + k];
        }
        __syncthreads();

        #pragma unroll 8
        for (int k = 0; k < 64; k++) {
            float4 hv = *(const float4*)&hs[k * 128 + gq * 4];
            float4 wv = *(const float4*)&ls[k * 16 + cq * 4];
            float hsv[4] = {hv.x, hv.y, hv.z, hv.w};
            float wsv[4] = {wv.x, wv.y, wv.z, wv.w};
            #pragma unroll
            for (int i = 0; i < 4; i++)
                #pragma unroll
                for (int j = 0; j < 4; j++)
                    acc[i][j] = fmaf(hsv[i], wsv[j], acc[i][j]);
        }
    }

    #pragma unroll
    for (int i = 0; i < 4; i++)
        #pragma unroll
        for (int j = 0; j < 4; j++)
            atomicAdd(&g_logits[(size_t)(g0 + gq * 4 + i) * Cc + cq * 4 + j],
                      acc[i][j]);
}

// ---------------------------------------------------------------------------
// K4: bias + log_softmax over [G, 16]
// ---------------------------------------------------------------------------
__global__ __launch_bounds__(256) void k4_lsm(const float* __restrict__ lb,
                                              float* __restrict__ out)
{
    const int tid = threadIdx.x;
    const int g   = blockIdx.x * 16 + (tid >> 4);
    const int c   = tid & 15;

    float s = g_logits[g * Cc + c] + lb[c];
    float m = s;
    #pragma unroll
    for (int o = 8; o > 0; o >>= 1)
        m = fmaxf(m, __shfl_xor_sync(0xffffffffu, m, o, 16));
    float se = expf(s - m);
    #pragma unroll
    for (int o = 8; o > 0; o >>= 1)
        se += __shfl_xor_sync(0xffffffffu, se, o, 16);
    out[g * Cc + c] = (s - m) - logf(se);
}

// ---------------------------------------------------------------------------
extern "C" void kernel_launch(void* const* d_in, const int* in_sizes, int n_in,
                              void* d_out, int out_size)
{
    const float* x  = (const float*)d_in[0];   // [G, N, F_IN]
    const int*   ei = (const int*)  d_in[1];   // [G, 2, E]
    const float* cw = (const float*)d_in[2];   // [F_OUT, F_IN]
    const float* cb = (const float*)d_in[3];   // [F_OUT]
    const float* lw = (const float*)d_in[4];   // [C, N*F_OUT]
    const float* lb = (const float*)d_in[5];   // [C]
    float* out = (float*)d_out;                // [G, C]

    k1_xw <<<dim3(Nn / 64, Gg), 256>>>(x, cw);
    k2a_csr<<<Gg, 512>>>(ei);
    k2b_agg<<<dim3(Gg, 4), 512>>>(cb);
    k3_cls<<<dim3(128, 2), 128>>>(lw);
    k4_lsm<<<16, 256>>>(lb, out);
}